// round 16
// baseline (speedup 1.0000x reference)
#include <cuda_runtime.h>
#include <cuda_bf16.h>
#include <cstdint>

// Problem constants (fixed by metadata): B=32, N=300, C=3, H=W=1024
#define BB 32
#define NN 300
#define HH 1024
#define WW 1024
#define NBOX (BB * NN)          // 9600
#define PLANE (1u << 20)        // 1024*1024
#define NCHUNK 32
#define CHROWS (HH / NCHUNK)    // 32 rows per chunk

// Scratch: per-chunk local column-prefix of (class2 - class1). 128 MiB.
__device__ float s_colpre[(size_t)BB * PLANE];
// Per-(batch, chunk, col) chunk totals -> exclusive prefix (offsets). 4 MiB.
// After kern_offsets, row (b, 0) is all zeros (exclusive prefix) — used as
// the canonical zero row by kern_boxes' unified path.
__device__ float s_chunktot[BB * NCHUNK * WW];

__device__ __forceinline__ int clampi(int v, int lo, int hi) {
    return v < lo ? lo : (v > hi ? hi : v);
}

// trunc-toward-zero then clamp — bit-exact vs the reference.
__device__ __forceinline__ void box_coords(const float* __restrict__ boxes, int i,
                                           int& x1, int& x2, int& y1, int& y2) {
    float cx = boxes[i * 4 + 0];
    float cy = boxes[i * 4 + 1];
    float w  = boxes[i * 4 + 2];
    float h  = boxes[i * 4 + 3];
    x1 = clampi((int)((cx - w * 0.5f) * (float)WW), 0, WW - 1);
    x2 = clampi((int)((cx + w * 0.5f) * (float)WW), 0, WW - 1);
    y1 = clampi((int)((cy - h * 0.5f) * (float)HH), 0, HH - 1);
    y2 = clampi((int)((cy + h * 0.5f) * (float)HH), 0, HH - 1);
}

// Kernel 1: segmented column-prefix of diff = seg[b,2] - seg[b,1], float4.
// grid = (2, NCHUNK, BB), block = 128 = 4 warps. Each WARP owns a 128-column
// window (32 lanes x float4) so the per-window write masking keeps 128-col
// granularity; each thread scans CHROWS=32 rows of its 4 columns with
// LDG.128 (.cs, evict-first) — 4x fewer L1tex wavefronts than scalar for the
// same bytes, at unchanged thread/block counts (262K threads, 2048 blocks).
// Chunk totals computed unconditionally; masked rows stored as STG.128.
__global__ void __launch_bounds__(128)
kern_colscan(const float* __restrict__ seg,
             const float* __restrict__ boxes,
             const float* __restrict__ conf,
             float* __restrict__ out) {
    const int b     = blockIdx.z;
    const int chunk = blockIdx.y;
    const int warp  = (int)threadIdx.x >> 5;
    const int lane  = (int)threadIdx.x & 31;
    const int c0    = blockIdx.x * 512 + warp * 128;   // warp's column window
    const int col   = c0 + lane * 4;                    // first of 4 columns
    const int r0    = chunk * CHROWS;

    // zero the output scalar once (ordered before kern_boxes' atomics by launch order)
    if ((blockIdx.x | blockIdx.y | blockIdx.z | threadIdx.x) == 0)
        out[0] = 0.0f;

    // Per-warp row mask (CHROWS=32 -> one word) restricted to this warp's
    // column window: a box marks rows only if [x1,x2) overlaps [c0,c0+128).
    __shared__ unsigned smask[4];
    if (lane == 0) smask[warp] = 0u;
    __syncwarp();
    for (int j = lane; j < NN; j += 32) {
        int i = b * NN + j;
        int x1, x2, y1, y2;
        box_coords(boxes, i, x1, x2, y1, y2);
        if ((conf[i] >= 0.3f) && (x2 > x1) && (y2 > y1) &&
            (x1 < c0 + 128) && (x2 > c0)) {
            int rt = y2 - 1;
            if ((unsigned)(rt - r0) < (unsigned)CHROWS)
                atomicOr(&smask[warp], 1u << (rt - r0));
            if (y1 > 0) {
                int rb = y1 - 1;
                if ((unsigned)(rb - r0) < (unsigned)CHROWS)
                    atomicOr(&smask[warp], 1u << (rb - r0));
            }
        }
    }
    __syncwarp();
    const unsigned m = smask[warp];

    const float4* __restrict__ p1 =
        (const float4*)(seg + ((size_t)(b * 3 + 1)) * PLANE + (size_t)r0 * WW + col);
    const float4* __restrict__ p2 =
        (const float4*)(seg + ((size_t)(b * 3 + 2)) * PLANE + (size_t)r0 * WW + col);
    float4* __restrict__ pc =
        (float4*)(s_colpre + ((size_t)b) * PLANE + (size_t)r0 * WW + col);
    const int RS = WW / 4;   // row stride in float4

    float4 run = make_float4(0.f, 0.f, 0.f, 0.f);
#pragma unroll
    for (int g = 0; g < CHROWS / 2; ++g) {
        float4 a0 = __ldcs(p1);
        float4 a1 = __ldcs(p1 + RS);
        float4 c0v = __ldcs(p2);
        float4 c1v = __ldcs(p2 + RS);
        run.x += c0v.x - a0.x; run.y += c0v.y - a0.y;
        run.z += c0v.z - a0.z; run.w += c0v.w - a0.w;
        if ((m >> (2 * g)) & 1u) pc[0] = run;
        run.x += c1v.x - a1.x; run.y += c1v.y - a1.y;
        run.z += c1v.z - a1.z; run.w += c1v.w - a1.w;
        if ((m >> (2 * g + 1)) & 1u) pc[RS] = run;
        p1 += 2 * RS;
        p2 += 2 * RS;
        pc += 2 * RS;
    }
    *(float4*)(s_chunktot + (b * NCHUNK + chunk) * WW + col) = run;
}

// Kernel 2: chunk totals -> per-column exclusive prefixes, in place.
// Batch-load all 32 values (independent LDGs, L2-resident), register prefix,
// store back. One thread per (batch, col).
__global__ void __launch_bounds__(512)
kern_offsets() {
    int idx = blockIdx.x * 512 + threadIdx.x;   // 0..BB*WW-1
    int b = idx >> 10;
    int col = idx & (WW - 1);
    float v[NCHUNK];
#pragma unroll
    for (int c = 0; c < NCHUNK; ++c)
        v[c] = s_chunktot[(b * NCHUNK + c) * WW + col];
    float run = 0.0f;
#pragma unroll
    for (int c = 0; c < NCHUNK; ++c) {
        float t = v[c];
        s_chunktot[(b * NCHUNK + c) * WW + col] = run;
        run += t;
    }
}

// Kernel 3: one block per box. Unified 4-stream segment reduce with float4
// interior loads: s = (top - bot) + (offt - offb). For y1==0, bot and offb
// both point at s_chunktot[b][0] (zeros after kern_offsets), so one code
// path covers every case. relu, conf weight, atomicAdd into the scalar.
__global__ void __launch_bounds__(128)
kern_boxes(const float* __restrict__ boxes,
           const float* __restrict__ conf,
           float* __restrict__ out) {
    int i = blockIdx.x;
    int x1, x2, y1, y2;
    box_coords(boxes, i, x1, x2, y1, y2);
    float cf = conf[i];
    if (!((cf >= 0.3f) && (x2 > x1) && (y2 > y1))) return;

    int b = i / NN;
    int rt = y2 - 1;
    int ct = rt / CHROWS;
    const float* __restrict__ top  = s_colpre  + ((size_t)b) * PLANE + (size_t)rt * WW;
    const float* __restrict__ offt = s_chunktot + (b * NCHUNK + ct) * WW;
    const float* __restrict__ bot;
    const float* __restrict__ offb;
    if (y1 > 0) {
        int rb = y1 - 1;
        int cb = rb / CHROWS;
        bot  = s_colpre  + ((size_t)b) * PLANE + (size_t)rb * WW;
        offb = s_chunktot + (b * NCHUNK + cb) * WW;
    } else {
        bot  = s_chunktot + b * NCHUNK * WW;   // chunk-0 offset row: zeros
        offb = bot;
    }

    float s = 0.0f;
    int tx = (int)threadIdx.x;
    int xa = (x1 + 3) & ~3;   // first float4-aligned pixel
    int xb = x2 & ~3;         // end of float4 region
    if (xa >= xb) {
        // narrow box: plain scalar
        for (int x = x1 + tx; x < x2; x += 128)
            s += (top[x] - bot[x]) + (offt[x] - offb[x]);
    } else {
        // scalar edges (<= 3 + 3 elements) on low threads
        int ne1 = xa - x1;
        int ne2 = x2 - xb;
        if (tx < ne1) {
            int x = x1 + tx;
            s += (top[x] - bot[x]) + (offt[x] - offb[x]);
        } else if (tx < ne1 + ne2) {
            int x = xb + (tx - ne1);
            s += (top[x] - bot[x]) + (offt[x] - offb[x]);
        }
        // float4 interior
        const float4* t4 = (const float4*)top;
        const float4* b4 = (const float4*)bot;
        const float4* ot4 = (const float4*)offt;
        const float4* ob4 = (const float4*)offb;
        for (int q = xa / 4 + tx; q < xb / 4; q += 128) {
            float4 a = t4[q], c = b4[q], u = ot4[q], v = ob4[q];
            s += (a.x - c.x) + (u.x - v.x);
            s += (a.y - c.y) + (u.y - v.y);
            s += (a.z - c.z) + (u.z - v.z);
            s += (a.w - c.w) + (u.w - v.w);
        }
    }

    __shared__ float red[4];
#pragma unroll
    for (int off = 16; off > 0; off >>= 1)
        s += __shfl_down_sync(0xFFFFFFFFu, s, off);
    if ((threadIdx.x & 31) == 0) red[threadIdx.x >> 5] = s;
    __syncthreads();
    if (threadIdx.x == 0) {
        float tsum = red[0] + red[1] + red[2] + red[3];
        float area = (float)((y2 - y1) * (x2 - x1));
        float pb = fmaxf(tsum / area, 0.0f) * cf;
        atomicAdd(out, pb * (1.0f / (float)NBOX));
    }
}

extern "C" void kernel_launch(void* const* d_in, const int* in_sizes, int n_in,
                              void* d_out, int out_size) {
    const float* boxes = (const float*)d_in[0];   // (32,300,4)
    const float* conf  = (const float*)d_in[1];   // (32,300)
    const float* seg   = (const float*)d_in[2];   // (32,3,1024,1024)
    float* out = (float*)d_out;

    dim3 gscan(2, NCHUNK, BB);
    kern_colscan<<<gscan, 128>>>(seg, boxes, conf, out);
    kern_offsets<<<(BB * WW) / 512, 512>>>();
    kern_boxes<<<NBOX, 128>>>(boxes, conf, out);
}